// round 1
// baseline (speedup 1.0000x reference)
#include <cuda_runtime.h>
#include <cstdint>

// Problem constants
constexpr int Bb = 8;
constexpr int Nn = 1024;
constexpr int Cc = 768;
constexpr int Hh = 12;
constexpr int HDd = 64;
constexpr int Vv = 8;

constexpr int M1  = Bb * Nn;       // 8192  rows for q / attn-out / proj
constexpr int MKV = Vv * Bb * Nn;  // 65536 rows for kv projection
constexpr int KVW = 2 * HDd;       // 128

// ---------------------------------------------------------------------------
// Scratch (device globals; no allocation allowed in kernel_launch)
// ---------------------------------------------------------------------------
__device__ float g_q[M1 * Cc];        // [B,N,C]   25 MB
__device__ float g_kv[MKV * KVW];     // [V,B,N,128] 33.5 MB
__device__ float g_ao[M1 * Cc];       // attention output [B,N,C] 25 MB

// ---------------------------------------------------------------------------
// SGEMM-NT: C[m,n] = sum_k A[m*K+k] * W[n*K+k] (+ bias[n])
// A: [M,K] row-major, W: [N,K] row-major (both K-contiguous -> coalesced)
// BM=BN=128, BK=8, 16x16 threads, 8x8 per-thread micro-tile, float4 loads.
// Requires M%128==0, N%128==0, K%8==0 (all true for this problem).
// ---------------------------------------------------------------------------
__global__ __launch_bounds__(256)
void sgemm_nt(const float* __restrict__ A,
              const float* __restrict__ W,
              const float* __restrict__ bias,
              float* __restrict__ C,
              int M, int N, int K)
{
    constexpr int BM = 128, BN = 128, BK = 8;
    __shared__ float As[BK][BM];
    __shared__ float Ws[BK][BN];

    const int t  = threadIdx.x;          // 0..255
    const int tx = t % 16;               // n-tile coordinate
    const int ty = t / 16;               // m-tile coordinate

    const int bm = blockIdx.y * BM;
    const int bn = blockIdx.x * BN;

    // Global load assignments: each thread loads one float4 of A and one of W
    // per k-tile.  row = t/2 in [0,128), k-offset = (t%2)*4.
    const int ldRow = t >> 1;
    const int ldK   = (t & 1) * 4;

    const float* Aptr = A + (size_t)(bm + ldRow) * K + ldK;
    const float* Wptr = W + (size_t)(bn + ldRow) * K + ldK;

    float acc[8][8];
    #pragma unroll
    for (int i = 0; i < 8; i++)
        #pragma unroll
        for (int j = 0; j < 8; j++)
            acc[i][j] = 0.0f;

    for (int kt = 0; kt < K; kt += BK) {
        // Prefetch global into registers
        float4 av = *reinterpret_cast<const float4*>(Aptr + kt);
        float4 wv = *reinterpret_cast<const float4*>(Wptr + kt);

        __syncthreads();   // previous tile's compute done
        As[ldK + 0][ldRow] = av.x;
        As[ldK + 1][ldRow] = av.y;
        As[ldK + 2][ldRow] = av.z;
        As[ldK + 3][ldRow] = av.w;
        Ws[ldK + 0][ldRow] = wv.x;
        Ws[ldK + 1][ldRow] = wv.y;
        Ws[ldK + 2][ldRow] = wv.z;
        Ws[ldK + 3][ldRow] = wv.w;
        __syncthreads();

        #pragma unroll
        for (int k = 0; k < BK; k++) {
            float am[8], wn[8];
            #pragma unroll
            for (int i = 0; i < 8; i++) am[i] = As[k][ty * 8 + i];
            #pragma unroll
            for (int j = 0; j < 8; j++) wn[j] = Ws[k][tx * 8 + j];
            #pragma unroll
            for (int i = 0; i < 8; i++)
                #pragma unroll
                for (int j = 0; j < 8; j++)
                    acc[i][j] = fmaf(am[i], wn[j], acc[i][j]);
        }
    }

    // Epilogue: optional bias, float4 stores
    #pragma unroll
    for (int i = 0; i < 8; i++) {
        const int gm = bm + ty * 8 + i;
        float* crow = C + (size_t)gm * N + bn + tx * 8;
        #pragma unroll
        for (int j = 0; j < 8; j += 4) {
            float4 v;
            v.x = acc[i][j + 0];
            v.y = acc[i][j + 1];
            v.z = acc[i][j + 2];
            v.w = acc[i][j + 3];
            if (bias) {
                const float* brow = bias + bn + tx * 8 + j;
                v.x += brow[0]; v.y += brow[1]; v.z += brow[2]; v.w += brow[3];
            }
            *reinterpret_cast<float4*>(crow + j) = v;
        }
    }
}

// ---------------------------------------------------------------------------
// Fused attention: one CTA per (b,n).
// q:  [B,N,C]   kvr: [V,B,N,128] (first 64 = k, last 64 = v)
// out[b,n,h*64+d] = sum_v softmax_v( q[b,n,h,:]·k[v,:] * 0.125 ) * v[v,d]
// ---------------------------------------------------------------------------
__global__ __launch_bounds__(256)
void attn_kernel(const float* __restrict__ q,
                 const float* __restrict__ kvr,
                 float* __restrict__ out)
{
    const int bn = blockIdx.x;           // b*N + n
    const int t  = threadIdx.x;          // 0..255

    __shared__ float sq[Cc];             // 768 floats
    __shared__ float skv[Vv][KVW];       // 8 x 128
    __shared__ float slog[Hh][Vv];
    __shared__ float sp[Hh][Vv];

    // Load q row (float4, 192 vec loads)
    {
        const float4* src = reinterpret_cast<const float4*>(q + (size_t)bn * Cc);
        float4* dst = reinterpret_cast<float4*>(sq);
        for (int i = t; i < Cc / 4; i += 256) dst[i] = src[i];
    }
    // Load all 8 kv rows (256 vec loads)
    {
        for (int i = t; i < Vv * KVW / 4; i += 256) {
            int v = i / (KVW / 4);
            int d4 = i % (KVW / 4);
            const float4* src = reinterpret_cast<const float4*>(
                kvr + ((size_t)v * (Bb * Nn) + bn) * KVW);
            reinterpret_cast<float4*>(skv[v])[d4] = src[d4];
        }
    }
    __syncthreads();

    // Logits: 96 (h,v) pairs, 64-wide dot each
    if (t < Hh * Vv) {
        const int h = t / Vv;
        const int v = t % Vv;
        float a0 = 0.f, a1 = 0.f;
        #pragma unroll
        for (int d = 0; d < HDd; d += 2) {
            a0 = fmaf(sq[h * HDd + d],     skv[v][d],     a0);
            a1 = fmaf(sq[h * HDd + d + 1], skv[v][d + 1], a1);
        }
        slog[h][v] = (a0 + a1) * 0.125f;
    }
    __syncthreads();

    // Softmax over V=8 per head
    if (t < Hh) {
        float mx = -1e30f;
        #pragma unroll
        for (int v = 0; v < Vv; v++) mx = fmaxf(mx, slog[t][v]);
        float e[Vv];
        float s = 0.f;
        #pragma unroll
        for (int v = 0; v < Vv; v++) { e[v] = __expf(slog[t][v] - mx); s += e[v]; }
        const float inv = 1.0f / s;
        #pragma unroll
        for (int v = 0; v < Vv; v++) sp[t][v] = e[v] * inv;
    }
    __syncthreads();

    // Mix: out[i] = sum_v p[h][v] * vvec[v][d],  h=i/64, d=i%64
    for (int i = t; i < Cc; i += 256) {
        const int h = i / HDd;
        const int d = i % HDd;
        float a = 0.f;
        #pragma unroll
        for (int v = 0; v < Vv; v++)
            a = fmaf(sp[h][v], skv[v][HDd + d], a);
        out[(size_t)bn * Cc + i] = a;
    }
}

// ---------------------------------------------------------------------------
// Launch
// Inputs (metadata order): x, variants_patches, Wq, Wkv, Wproj, bproj, num_layer
// ---------------------------------------------------------------------------
extern "C" void kernel_launch(void* const* d_in, const int* in_sizes, int n_in,
                              void* d_out, int out_size)
{
    const float* x   = (const float*)d_in[0];   // [B,N,C]
    const float* vp  = (const float*)d_in[1];   // [V,B,N,C]
    const float* Wq  = (const float*)d_in[2];   // [C,C]
    const float* Wkv = (const float*)d_in[3];   // [128,C]
    const float* Wp  = (const float*)d_in[4];   // [C,C]
    const float* bp  = (const float*)d_in[5];   // [C]
    float* out = (float*)d_out;                 // [B,N,C]

    float *q, *kv, *ao;
    cudaGetSymbolAddress((void**)&q,  g_q);
    cudaGetSymbolAddress((void**)&kv, g_kv);
    cudaGetSymbolAddress((void**)&ao, g_ao);

    // 1) q = x @ Wq^T          : [8192,768] = [8192,768]x[768,768]^T
    sgemm_nt<<<dim3(Cc / 128, M1 / 128), 256>>>(x, Wq, nullptr, q, M1, Cc, Cc);

    // 2) kv = vp_flat @ Wkv^T  : [65536,128] = [65536,768]x[128,768]^T
    //    (variants_patches flattened over (V,B,N) — transpose handled by indexing)
    sgemm_nt<<<dim3(KVW / 128, MKV / 128), 256>>>(vp, Wkv, nullptr, kv, MKV, KVW, Cc);

    // 3) fused attention per (b,n)
    attn_kernel<<<M1, 256>>>(q, kv, ao);

    // 4) out = ao @ Wproj^T + bproj
    sgemm_nt<<<dim3(Cc / 128, M1 / 128), 256>>>(ao, Wp, bp, out, M1, Cc, Cc);
}

// round 2
// speedup vs baseline: 2.6709x; 2.6709x over previous
#include <cuda_runtime.h>
#include <cstdint>

// Problem constants
constexpr int Bb = 8;
constexpr int Nn = 1024;
constexpr int Cc = 768;
constexpr int Hh = 12;
constexpr int HDd = 64;
constexpr int Vv = 8;

constexpr int M1  = Bb * Nn;       // 8192
constexpr int MKV = Vv * Bb * Nn;  // 65536
constexpr int KVW = 2 * HDd;       // 128

// ---------------------------------------------------------------------------
// Scratch (device globals; no allocation allowed)
// ---------------------------------------------------------------------------
__device__ float g_q[M1 * Cc];
__device__ float g_kv[MKV * KVW];
__device__ float g_ao[M1 * Cc];

__device__ __forceinline__ unsigned f2tf32(float f) {
    unsigned r;
    asm volatile("cvt.rna.tf32.f32 %0, %1;" : "=r"(r) : "f"(f));
    return r;
}

#define MMA_TF32(c, a, b)                                                   \
    asm volatile(                                                           \
        "mma.sync.aligned.m16n8k8.row.col.f32.tf32.tf32.f32 "               \
        "{%0,%1,%2,%3}, {%4,%5,%6,%7}, {%8,%9}, {%0,%1,%2,%3};\n"           \
        : "+f"((c)[0]), "+f"((c)[1]), "+f"((c)[2]), "+f"((c)[3])            \
        : "r"((a)[0]), "r"((a)[1]), "r"((a)[2]), "r"((a)[3]),               \
          "r"((b)[0]), "r"((b)[1]))

// ---------------------------------------------------------------------------
// TF32 tensor-core GEMM-NT: C[m,n] = sum_k A[m,k] * W[n,k] (+ bias[n])
// CTA tile 128x128, BK=16, 8 warps (4 along M x 2 along N), warp tile 32x64.
// Requires M%128==0, N%128==0, K%16==0.
// ---------------------------------------------------------------------------
__global__ __launch_bounds__(256)
void tgemm_nt(const float* __restrict__ A,
              const float* __restrict__ W,
              const float* __restrict__ bias,
              float* __restrict__ C,
              int M, int N, int K)
{
    // smem tiles stored row-major [row][k], padded 16 -> 20 (conflict-free frag loads)
    __shared__ unsigned As[128][20];
    __shared__ unsigned Ws[128][20];

    const int t    = threadIdx.x;
    const int wid  = t >> 5;
    const int lane = t & 31;
    const int lq   = lane >> 2;   // 0..7
    const int lr   = lane & 3;    // 0..3

    const int bm = blockIdx.y * 128;
    const int bn = blockIdx.x * 128;

    const int warp_m = (wid & 3) * 32;   // 0,32,64,96
    const int warp_n = (wid >> 2) * 64;  // 0,64

    // Global load mapping: 512 float4 per tile per matrix, 2 per thread.
    // idx -> row = idx>>2, kq = idx&3 (k offset = kq*4)
    const int i0 = t, i1 = t + 256;
    const int r0 = i0 >> 2, kq0 = i0 & 3;
    const int r1 = i1 >> 2, kq1 = i1 & 3;

    const float* A0 = A + (size_t)(bm + r0) * K + kq0 * 4;
    const float* A1 = A + (size_t)(bm + r1) * K + kq1 * 4;
    const float* W0 = W + (size_t)(bn + r0) * K + kq0 * 4;
    const float* W1 = W + (size_t)(bn + r1) * K + kq1 * 4;

    float acc[2][8][4];
    #pragma unroll
    for (int mt = 0; mt < 2; mt++)
        #pragma unroll
        for (int nt = 0; nt < 8; nt++)
            #pragma unroll
            for (int i = 0; i < 4; i++)
                acc[mt][nt][i] = 0.0f;

    float4 av0, av1, wv0, wv1;

    // ---- preload tile 0 ----
    av0 = *reinterpret_cast<const float4*>(A0);
    av1 = *reinterpret_cast<const float4*>(A1);
    wv0 = *reinterpret_cast<const float4*>(W0);
    wv1 = *reinterpret_cast<const float4*>(W1);

    auto store_tile = [&](const float4& a0v, const float4& a1v,
                          const float4& w0v, const float4& w1v) {
        uint4 u;
        u.x = f2tf32(a0v.x); u.y = f2tf32(a0v.y); u.z = f2tf32(a0v.z); u.w = f2tf32(a0v.w);
        *reinterpret_cast<uint4*>(&As[r0][kq0 * 4]) = u;
        u.x = f2tf32(a1v.x); u.y = f2tf32(a1v.y); u.z = f2tf32(a1v.z); u.w = f2tf32(a1v.w);
        *reinterpret_cast<uint4*>(&As[r1][kq1 * 4]) = u;
        u.x = f2tf32(w0v.x); u.y = f2tf32(w0v.y); u.z = f2tf32(w0v.z); u.w = f2tf32(w0v.w);
        *reinterpret_cast<uint4*>(&Ws[r0][kq0 * 4]) = u;
        u.x = f2tf32(w1v.x); u.y = f2tf32(w1v.y); u.z = f2tf32(w1v.z); u.w = f2tf32(w1v.w);
        *reinterpret_cast<uint4*>(&Ws[r1][kq1 * 4]) = u;
    };

    store_tile(av0, av1, wv0, wv1);
    __syncthreads();

    for (int kt = 0; kt < K; kt += 16) {
        const bool has_next = (kt + 16) < K;
        if (has_next) {
            av0 = *reinterpret_cast<const float4*>(A0 + kt + 16);
            av1 = *reinterpret_cast<const float4*>(A1 + kt + 16);
            wv0 = *reinterpret_cast<const float4*>(W0 + kt + 16);
            wv1 = *reinterpret_cast<const float4*>(W1 + kt + 16);
        }

        // compute 2 x k8 steps from smem
        #pragma unroll
        for (int kk = 0; kk < 16; kk += 8) {
            unsigned afr[2][4];
            #pragma unroll
            for (int mt = 0; mt < 2; mt++) {
                const int row = warp_m + mt * 16 + lq;
                afr[mt][0] = As[row][kk + lr];
                afr[mt][1] = As[row + 8][kk + lr];
                afr[mt][2] = As[row][kk + 4 + lr];
                afr[mt][3] = As[row + 8][kk + 4 + lr];
            }
            unsigned bfr[8][2];
            #pragma unroll
            for (int nt = 0; nt < 8; nt++) {
                const int col = warp_n + nt * 8 + lq;
                bfr[nt][0] = Ws[col][kk + lr];
                bfr[nt][1] = Ws[col][kk + 4 + lr];
            }
            #pragma unroll
            for (int mt = 0; mt < 2; mt++)
                #pragma unroll
                for (int nt = 0; nt < 8; nt++)
                    MMA_TF32(acc[mt][nt], afr[mt], bfr[nt]);
        }

        __syncthreads();
        if (has_next) {
            store_tile(av0, av1, wv0, wv1);
            __syncthreads();
        }
    }

    // ---- epilogue ----
    #pragma unroll
    for (int mt = 0; mt < 2; mt++) {
        const int row0 = bm + warp_m + mt * 16 + lq;
        #pragma unroll
        for (int nt = 0; nt < 8; nt++) {
            const int col = bn + warp_n + nt * 8 + 2 * lr;
            float b0 = 0.f, b1 = 0.f;
            if (bias) { b0 = bias[col]; b1 = bias[col + 1]; }
            float2 v01 = make_float2(acc[mt][nt][0] + b0, acc[mt][nt][1] + b1);
            float2 v23 = make_float2(acc[mt][nt][2] + b0, acc[mt][nt][3] + b1);
            *reinterpret_cast<float2*>(C + (size_t)row0 * N + col) = v01;
            *reinterpret_cast<float2*>(C + (size_t)(row0 + 8) * N + col) = v23;
        }
    }
}

// ---------------------------------------------------------------------------
// Fused attention: one CTA per (b,n).  (unchanged, ~noise in the profile)
// ---------------------------------------------------------------------------
__global__ __launch_bounds__(256)
void attn_kernel(const float* __restrict__ q,
                 const float* __restrict__ kvr,
                 float* __restrict__ out)
{
    const int bn = blockIdx.x;
    const int t  = threadIdx.x;

    __shared__ float sq[Cc];
    __shared__ float skv[Vv][KVW];
    __shared__ float slog[Hh][Vv];
    __shared__ float sp[Hh][Vv];

    {
        const float4* src = reinterpret_cast<const float4*>(q + (size_t)bn * Cc);
        float4* dst = reinterpret_cast<float4*>(sq);
        for (int i = t; i < Cc / 4; i += 256) dst[i] = src[i];
    }
    {
        for (int i = t; i < Vv * KVW / 4; i += 256) {
            int v = i / (KVW / 4);
            int d4 = i % (KVW / 4);
            const float4* src = reinterpret_cast<const float4*>(
                kvr + ((size_t)v * (Bb * Nn) + bn) * KVW);
            reinterpret_cast<float4*>(skv[v])[d4] = src[d4];
        }
    }
    __syncthreads();

    if (t < Hh * Vv) {
        const int h = t / Vv;
        const int v = t % Vv;
        float a0 = 0.f, a1 = 0.f;
        #pragma unroll
        for (int d = 0; d < HDd; d += 2) {
            a0 = fmaf(sq[h * HDd + d],     skv[v][d],     a0);
            a1 = fmaf(sq[h * HDd + d + 1], skv[v][d + 1], a1);
        }
        slog[h][v] = (a0 + a1) * 0.125f;
    }
    __syncthreads();

    if (t < Hh) {
        float mx = -1e30f;
        #pragma unroll
        for (int v = 0; v < Vv; v++) mx = fmaxf(mx, slog[t][v]);
        float e[Vv];
        float s = 0.f;
        #pragma unroll
        for (int v = 0; v < Vv; v++) { e[v] = __expf(slog[t][v] - mx); s += e[v]; }
        const float inv = 1.0f / s;
        #pragma unroll
        for (int v = 0; v < Vv; v++) sp[t][v] = e[v] * inv;
    }
    __syncthreads();

    for (int i = t; i < Cc; i += 256) {
        const int h = i / HDd;
        const int d = i % HDd;
        float a = 0.f;
        #pragma unroll
        for (int v = 0; v < Vv; v++)
            a = fmaf(sp[h][v], skv[v][HDd + d], a);
        out[(size_t)bn * Cc + i] = a;
    }
}

// ---------------------------------------------------------------------------
// Launch
// ---------------------------------------------------------------------------
extern "C" void kernel_launch(void* const* d_in, const int* in_sizes, int n_in,
                              void* d_out, int out_size)
{
    const float* x   = (const float*)d_in[0];
    const float* vp  = (const float*)d_in[1];
    const float* Wq  = (const float*)d_in[2];
    const float* Wkv = (const float*)d_in[3];
    const float* Wp  = (const float*)d_in[4];
    const float* bp  = (const float*)d_in[5];
    float* out = (float*)d_out;

    float *q, *kv, *ao;
    cudaGetSymbolAddress((void**)&q,  g_q);
    cudaGetSymbolAddress((void**)&kv, g_kv);
    cudaGetSymbolAddress((void**)&ao, g_ao);

    // 1) q = x @ Wq^T
    tgemm_nt<<<dim3(Cc / 128, M1 / 128), 256>>>(x, Wq, nullptr, q, M1, Cc, Cc);

    // 2) kv = vp_flat @ Wkv^T
    tgemm_nt<<<dim3(KVW / 128, MKV / 128), 256>>>(vp, Wkv, nullptr, kv, MKV, KVW, Cc);

    // 3) fused attention per (b,n)
    attn_kernel<<<M1, 256>>>(q, kv, ao);

    // 4) out = ao @ Wproj^T + bproj
    tgemm_nt<<<dim3(Cc / 128, M1 / 128), 256>>>(ao, Wp, bp, out, M1, Cc, Cc);
}

// round 4
// speedup vs baseline: 3.2695x; 1.2241x over previous
#include <cuda_runtime.h>
#include <cstdint>

// Problem constants
constexpr int Bb = 8;
constexpr int Nn = 1024;
constexpr int Cc = 768;
constexpr int Hh = 12;
constexpr int HDd = 64;
constexpr int Vv = 8;

constexpr int M1  = Bb * Nn;       // 8192
constexpr int MKV = Vv * Bb * Nn;  // 65536
constexpr int KVW = 2 * HDd;       // 128

// ---------------------------------------------------------------------------
// Scratch
// ---------------------------------------------------------------------------
__device__ float g_q[M1 * Cc];
__device__ float g_kv[MKV * KVW];
__device__ float g_ao[M1 * Cc];

__device__ __forceinline__ uint32_t smem_u32(const void* p) {
    uint32_t a;
    asm("{ .reg .u64 t; cvta.to.shared.u64 t, %1; cvt.u32.u64 %0, t; }"
        : "=r"(a) : "l"(p));
    return a;
}

__device__ __forceinline__ unsigned f2tf32(float f) {
    unsigned r;
    asm volatile("cvt.rna.tf32.f32 %0, %1;" : "=r"(r) : "f"(f));
    return r;
}

#define CP_ASYNC16(dst, src)                                                  \
    asm volatile("cp.async.ca.shared.global [%0], [%1], 16;\n"                \
                 :: "r"(dst), "l"(src))
#define CP_COMMIT() asm volatile("cp.async.commit_group;\n" ::: "memory")
#define CP_WAIT1()  asm volatile("cp.async.wait_group 1;\n" ::: "memory")

#define MMA_TF32(c, a, b)                                                   \
    asm volatile(                                                           \
        "mma.sync.aligned.m16n8k8.row.col.f32.tf32.tf32.f32 "               \
        "{%0,%1,%2,%3}, {%4,%5,%6,%7}, {%8,%9}, {%0,%1,%2,%3};\n"           \
        : "+f"((c)[0]), "+f"((c)[1]), "+f"((c)[2]), "+f"((c)[3])            \
        : "r"((a)[0]), "r"((a)[1]), "r"((a)[2]), "r"((a)[3]),               \
          "r"((b)[0]), "r"((b)[1]))

// ---------------------------------------------------------------------------
// TF32 warp-MMA GEMM-NT with cp.async 3-stage pipeline.
// C[m,n] = sum_k A[m,k] * W[n,k] (+ bias[n])
// CTA tile 128x128, BK=16, 8 warps (4M x 2N), warp tile 32x64.
// Smem rows padded 16 -> 20 floats (80B, 16B-aligned for cp.async).
// Requires M%128==0, N%128==0, K%16==0.
// ---------------------------------------------------------------------------
constexpr int STAGES = 3;
constexpr int ROWPAD = 20;                            // floats per smem row
constexpr int TILE_FLOATS = 128 * ROWPAD;             // per matrix per stage
constexpr int GEMM_SMEM = STAGES * 2 * TILE_FLOATS * 4;  // 61440 bytes

__global__ __launch_bounds__(256, 2)
void tgemm_nt(const float* __restrict__ A,
              const float* __restrict__ W,
              const float* __restrict__ bias,
              float* __restrict__ C,
              int M, int N, int K)
{
    extern __shared__ float sm[];
    // layout: [stage][A(2560f) then W(2560f)]
    const uint32_t sb = smem_u32(sm);

    const int t    = threadIdx.x;
    const int wid  = t >> 5;
    const int lane = t & 31;
    const int lq   = lane >> 2;   // 0..7
    const int lr   = lane & 3;    // 0..3

    const int bm = blockIdx.y * 128;
    const int bn = blockIdx.x * 128;

    const int warp_m = (wid & 3) * 32;
    const int warp_n = (wid >> 2) * 64;

    // cp.async mapping: 512 16B-chunks per matrix per tile; 2 per thread.
    // chunk f: row = f>>2, c = f&3 (k offset c*4)
    const int f0 = t, f1 = t + 256;
    const int r0 = f0 >> 2, c0 = f0 & 3;
    const int r1 = f1 >> 2, c1 = f1 & 3;

    const float* A0 = A + (size_t)(bm + r0) * K + c0 * 4;
    const float* A1 = A + (size_t)(bm + r1) * K + c1 * 4;
    const float* W0 = W + (size_t)(bn + r0) * K + c0 * 4;
    const float* W1 = W + (size_t)(bn + r1) * K + c1 * 4;

    const uint32_t dA0 = (uint32_t)(r0 * ROWPAD + c0 * 4) * 4;
    const uint32_t dA1 = (uint32_t)(r1 * ROWPAD + c1 * 4) * 4;
    const uint32_t dW0 = dA0 + TILE_FLOATS * 4;
    const uint32_t dW1 = dA1 + TILE_FLOATS * 4;

    auto issue_tile = [&](int kt, int stage) {
        const uint32_t base = sb + (uint32_t)stage * 2 * TILE_FLOATS * 4;
        const size_t ko = (size_t)kt * 16;
        CP_ASYNC16(base + dA0, A0 + ko);
        CP_ASYNC16(base + dA1, A1 + ko);
        CP_ASYNC16(base + dW0, W0 + ko);
        CP_ASYNC16(base + dW1, W1 + ko);
    };

    float acc[2][8][4];
    #pragma unroll
    for (int mt = 0; mt < 2; mt++)
        #pragma unroll
        for (int nt = 0; nt < 8; nt++)
            #pragma unroll
            for (int i = 0; i < 4; i++)
                acc[mt][nt][i] = 0.0f;

    const int NT = K / 16;

    // prologue: stages 0,1
    issue_tile(0, 0); CP_COMMIT();
    issue_tile(1, 1); CP_COMMIT();

    for (int kt = 0; kt < NT; kt++) {
        CP_WAIT1();
        __syncthreads();

        const int stage = kt % STAGES;
        const float* As = sm + (size_t)stage * 2 * TILE_FLOATS;
        const float* Ws = As + TILE_FLOATS;

        #pragma unroll
        for (int kk = 0; kk < 16; kk += 8) {
            unsigned afr[2][4];
            #pragma unroll
            for (int mt = 0; mt < 2; mt++) {
                const int row = warp_m + mt * 16 + lq;
                afr[mt][0] = f2tf32(As[row * ROWPAD + kk + lr]);
                afr[mt][1] = f2tf32(As[(row + 8) * ROWPAD + kk + lr]);
                afr[mt][2] = f2tf32(As[row * ROWPAD + kk + 4 + lr]);
                afr[mt][3] = f2tf32(As[(row + 8) * ROWPAD + kk + 4 + lr]);
            }
            unsigned bfr[8][2];
            #pragma unroll
            for (int nt = 0; nt < 8; nt++) {
                const int col = warp_n + nt * 8 + lq;
                bfr[nt][0] = f2tf32(Ws[col * ROWPAD + kk + lr]);
                bfr[nt][1] = f2tf32(Ws[col * ROWPAD + kk + 4 + lr]);
            }
            #pragma unroll
            for (int mt = 0; mt < 2; mt++)
                #pragma unroll
                for (int nt = 0; nt < 8; nt++)
                    MMA_TF32(acc[mt][nt], afr[mt], bfr[nt]);
        }

        __syncthreads();
        if (kt + 2 < NT) issue_tile(kt + 2, (kt + 2) % STAGES);
        CP_COMMIT();   // always commit (empty groups keep the count in step)
    }

    // epilogue
    #pragma unroll
    for (int mt = 0; mt < 2; mt++) {
        const int row0 = bm + warp_m + mt * 16 + lq;
        #pragma unroll
        for (int nt = 0; nt < 8; nt++) {
            const int col = bn + warp_n + nt * 8 + 2 * lr;
            float b0 = 0.f, b1 = 0.f;
            if (bias) { b0 = bias[col]; b1 = bias[col + 1]; }
            float2 v01 = make_float2(acc[mt][nt][0] + b0, acc[mt][nt][1] + b1);
            float2 v23 = make_float2(acc[mt][nt][2] + b0, acc[mt][nt][3] + b1);
            *reinterpret_cast<float2*>(C + (size_t)row0 * N + col) = v01;
            *reinterpret_cast<float2*>(C + (size_t)(row0 + 8) * N + col) = v23;
        }
    }
}

// ---------------------------------------------------------------------------
// Fused attention: one CTA per (b,n). Logits split 8 lanes per (h,v) dot.
// ---------------------------------------------------------------------------
__global__ __launch_bounds__(256)
void attn_kernel(const float* __restrict__ q,
                 const float* __restrict__ kvr,
                 float* __restrict__ out)
{
    const int bn = blockIdx.x;
    const int t  = threadIdx.x;

    __shared__ float sq[Cc];
    __shared__ float skv[Vv][KVW];
    __shared__ float slog[Hh * Vv];
    __shared__ float sp[Hh][Vv];

    {
        const float4* src = reinterpret_cast<const float4*>(q + (size_t)bn * Cc);
        float4* dst = reinterpret_cast<float4*>(sq);
        for (int i = t; i < Cc / 4; i += 256) dst[i] = src[i];
    }
    {
        for (int i = t; i < Vv * KVW / 4; i += 256) {
            int v = i / (KVW / 4);
            int d4 = i % (KVW / 4);
            const float4* src = reinterpret_cast<const float4*>(
                kvr + ((size_t)v * (Bb * Nn) + bn) * KVW);
            reinterpret_cast<float4*>(skv[v])[d4] = src[d4];
        }
    }
    __syncthreads();

    // Logits: 96 (h,v) pairs x 8-lane split = 768 tasks; 3 per thread.
    #pragma unroll
    for (int rep = 0; rep < 3; rep++) {
        const int task = t + rep * 256;
        const int pair = task >> 3;          // 0..95
        const int sub  = task & 7;           // 0..7 (== lane&7)
        const int h = pair / Vv;
        const int v = pair % Vv;
        float a = 0.f;
        #pragma unroll
        for (int j = 0; j < 8; j++)
            a = fmaf(sq[h * HDd + sub * 8 + j], skv[v][sub * 8 + j], a);
        a += __shfl_down_sync(0xffffffffu, a, 4);
        a += __shfl_down_sync(0xffffffffu, a, 2);
        a += __shfl_down_sync(0xffffffffu, a, 1);
        if (sub == 0) slog[pair] = a * 0.125f;
    }
    __syncthreads();

    if (t < Hh) {
        float mx = -1e30f;
        #pragma unroll
        for (int v = 0; v < Vv; v++) mx = fmaxf(mx, slog[t * Vv + v]);
        float e[Vv];
        float s = 0.f;
        #pragma unroll
        for (int v = 0; v < Vv; v++) {
            e[v] = __expf(slog[t * Vv + v] - mx);
            s += e[v];
        }
        const float inv = 1.0f / s;
        #pragma unroll
        for (int v = 0; v < Vv; v++) sp[t][v] = e[v] * inv;
    }
    __syncthreads();

    #pragma unroll
    for (int rep = 0; rep < 3; rep++) {
        const int i = t + rep * 256;
        const int h = i / HDd;
        const int d = i % HDd;
        float a = 0.f;
        #pragma unroll
        for (int v = 0; v < Vv; v++)
            a = fmaf(sp[h][v], skv[v][HDd + d], a);
        out[(size_t)bn * Cc + i] = a;
    }
}

// ---------------------------------------------------------------------------
// Launch
// ---------------------------------------------------------------------------
extern "C" void kernel_launch(void* const* d_in, const int* in_sizes, int n_in,
                              void* d_out, int out_size)
{
    const float* x   = (const float*)d_in[0];
    const float* vp  = (const float*)d_in[1];
    const float* Wq  = (const float*)d_in[2];
    const float* Wkv = (const float*)d_in[3];
    const float* Wp  = (const float*)d_in[4];
    const float* bp  = (const float*)d_in[5];
    float* out = (float*)d_out;

    float *q, *kv, *ao;
    cudaGetSymbolAddress((void**)&q,  g_q);
    cudaGetSymbolAddress((void**)&kv, g_kv);
    cudaGetSymbolAddress((void**)&ao, g_ao);

    cudaFuncSetAttribute(tgemm_nt,
                         cudaFuncAttributeMaxDynamicSharedMemorySize,
                         GEMM_SMEM);

    // 1) q = x @ Wq^T
    tgemm_nt<<<dim3(Cc / 128, M1 / 128), 256, GEMM_SMEM>>>(
        x, Wq, nullptr, q, M1, Cc, Cc);

    // 2) kv = vp_flat @ Wkv^T
    tgemm_nt<<<dim3(KVW / 128, MKV / 128), 256, GEMM_SMEM>>>(
        vp, Wkv, nullptr, kv, MKV, KVW, Cc);

    // 3) fused attention per (b,n)
    attn_kernel<<<M1, 256>>>(q, kv, ao);

    // 4) out = ao @ Wproj^T + bproj
    tgemm_nt<<<dim3(Cc / 128, M1 / 128), 256, GEMM_SMEM>>>(
        ao, Wp, bp, out, M1, Cc, Cc);
}

// round 5
// speedup vs baseline: 3.6999x; 1.1316x over previous
#include <cuda_runtime.h>
#include <cstdint>

// Problem constants
constexpr int Bb = 8;
constexpr int Nn = 1024;
constexpr int Cc = 768;
constexpr int Hh = 12;
constexpr int HDd = 64;
constexpr int Vv = 8;

constexpr int M1  = Bb * Nn;       // 8192
constexpr int MKV = Vv * Bb * Nn;  // 65536
constexpr int KVW = 2 * HDd;       // 128

// ---------------------------------------------------------------------------
// Scratch
// ---------------------------------------------------------------------------
__device__ float g_q[M1 * Cc];
__device__ float g_kv[MKV * KVW];
__device__ float g_ao[M1 * Cc];
__device__ float g_wq[Cc * Cc];     // tf32-rounded weights
__device__ float g_wkv[KVW * Cc];
__device__ float g_wp[Cc * Cc];

__device__ __forceinline__ uint32_t smem_u32(const void* p) {
    uint32_t a;
    asm("{ .reg .u64 t; cvta.to.shared.u64 t, %1; cvt.u32.u64 %0, t; }"
        : "=r"(a) : "l"(p));
    return a;
}

__device__ __forceinline__ unsigned f2tf32(float f) {
    unsigned r;
    asm volatile("cvt.rna.tf32.f32 %0, %1;" : "=r"(r) : "f"(f));
    return r;
}

#define CP_ASYNC16(dst, src)                                                  \
    asm volatile("cp.async.ca.shared.global [%0], [%1], 16;\n"                \
                 :: "r"(dst), "l"(src))
#define CP_COMMIT() asm volatile("cp.async.commit_group;\n" ::: "memory")
#define CP_WAIT1()  asm volatile("cp.async.wait_group 1;\n" ::: "memory")

#define MMA_TF32(c, a, b)                                                   \
    asm volatile(                                                           \
        "mma.sync.aligned.m16n8k8.row.col.f32.tf32.tf32.f32 "               \
        "{%0,%1,%2,%3}, {%4,%5,%6,%7}, {%8,%9}, {%0,%1,%2,%3};\n"           \
        : "+f"((c)[0]), "+f"((c)[1]), "+f"((c)[2]), "+f"((c)[3])            \
        : "r"((a)[0]), "r"((a)[1]), "r"((a)[2]), "r"((a)[3]),               \
          "r"((b)[0]), "r"((b)[1]))

#define LDSM_X4(r0, r1, r2, r3, addr)                                       \
    asm volatile(                                                           \
        "ldmatrix.sync.aligned.m8n8.x4.shared.b16 {%0,%1,%2,%3}, [%4];"     \
        : "=r"(r0), "=r"(r1), "=r"(r2), "=r"(r3) : "r"(addr))

// ---------------------------------------------------------------------------
// TF32 warp-MMA GEMM-NT, cp.async 3-stage pipeline + ldmatrix fragments.
// C[m,n] = sum_k A[m,k] * W[n,k] (+ bias[n]);  W must be tf32-pre-rounded.
// CTA tile 128x128, BK=16, 8 warps (4M x 2N), warp tile 32x64.
// Smem rows padded 16 -> 20 floats (80B: ldmatrix rows hit all 32 banks).
// ---------------------------------------------------------------------------
constexpr int STAGES = 3;
constexpr int ROWPAD = 20;
constexpr int TILE_FLOATS = 128 * ROWPAD;
constexpr int GEMM_SMEM = STAGES * 2 * TILE_FLOATS * 4;  // 61440 bytes
constexpr int MT_STRIDE = 16 * ROWPAD * 4;               // bytes per 16 rows

__global__ __launch_bounds__(256, 2)
void tgemm_nt(const float* __restrict__ A,
              const float* __restrict__ W,
              const float* __restrict__ bias,
              float* __restrict__ C,
              int M, int N, int K)
{
    extern __shared__ float sm[];
    const uint32_t sb = smem_u32(sm);

    const int t    = threadIdx.x;
    const int wid  = t >> 5;
    const int lane = t & 31;
    const int lq   = lane >> 2;
    const int lr   = lane & 3;

    const int bm = blockIdx.y * 128;
    const int bn = blockIdx.x * 128;

    const int warp_m = (wid & 3) * 32;
    const int warp_n = (wid >> 2) * 64;

    // cp.async mapping: 512 16B chunks per matrix per tile; 2 per thread.
    const int f0 = t, f1 = t + 256;
    const int r0 = f0 >> 2, c0 = f0 & 3;
    const int r1 = f1 >> 2, c1 = f1 & 3;

    const float* A0 = A + (size_t)(bm + r0) * K + c0 * 4;
    const float* A1 = A + (size_t)(bm + r1) * K + c1 * 4;
    const float* W0 = W + (size_t)(bn + r0) * K + c0 * 4;
    const float* W1 = W + (size_t)(bn + r1) * K + c1 * 4;

    const uint32_t dA0 = (uint32_t)(r0 * ROWPAD + c0 * 4) * 4;
    const uint32_t dA1 = (uint32_t)(r1 * ROWPAD + c1 * 4) * 4;
    const uint32_t dW0 = dA0 + TILE_FLOATS * 4;
    const uint32_t dW1 = dA1 + TILE_FLOATS * 4;

    auto issue_tile = [&](int kt, int stage) {
        const uint32_t base = sb + (uint32_t)stage * 2 * TILE_FLOATS * 4;
        const size_t ko = (size_t)kt * 16;
        CP_ASYNC16(base + dA0, A0 + ko);
        CP_ASYNC16(base + dA1, A1 + ko);
        CP_ASYNC16(base + dW0, W0 + ko);
        CP_ASYNC16(base + dW1, W1 + ko);
    };

    // ldmatrix per-lane address offsets (bytes, within a stage)
    // A frag (8x4 tf32 tiles): row = warp_m [+ mt*16] + ((lane>>3)&1)*8 + (lane&7)
    //                          col = (lane>>4)*4 [+ kk]
    const uint32_t aOff =
        (uint32_t)((warp_m + ((lane >> 3) & 1) * 8 + (lane & 7)) * ROWPAD
                   + (lane >> 4) * 4) * 4;
    // B frag pairs: col = warp_n [+ p*16] + (lane>>4)*8 + (lane&7)
    //               k   = ((lane>>3)&1)*4 [+ kk]
    const uint32_t bOff =
        (uint32_t)((warp_n + (lane >> 4) * 8 + (lane & 7)) * ROWPAD
                   + ((lane >> 3) & 1) * 4) * 4
        + TILE_FLOATS * 4;

    float acc[2][8][4];
    #pragma unroll
    for (int mt = 0; mt < 2; mt++)
        #pragma unroll
        for (int nt = 0; nt < 8; nt++)
            #pragma unroll
            for (int i = 0; i < 4; i++)
                acc[mt][nt][i] = 0.0f;

    const int NT = K / 16;

    issue_tile(0, 0); CP_COMMIT();
    issue_tile(1, 1); CP_COMMIT();

    for (int kt = 0; kt < NT; kt++) {
        CP_WAIT1();
        __syncthreads();

        const int stage = kt % STAGES;
        const uint32_t stBase = sb + (uint32_t)stage * 2 * TILE_FLOATS * 4;

        #pragma unroll
        for (int kk = 0; kk < 16; kk += 8) {
            const uint32_t kOfs = kk * 4;

            unsigned afr[2][4];
            #pragma unroll
            for (int mt = 0; mt < 2; mt++) {
                LDSM_X4(afr[mt][0], afr[mt][1], afr[mt][2], afr[mt][3],
                        stBase + aOff + mt * MT_STRIDE + kOfs);
                afr[mt][0] = f2tf32(__uint_as_float(afr[mt][0]));
                afr[mt][1] = f2tf32(__uint_as_float(afr[mt][1]));
                afr[mt][2] = f2tf32(__uint_as_float(afr[mt][2]));
                afr[mt][3] = f2tf32(__uint_as_float(afr[mt][3]));
            }
            unsigned bfr[8][2];
            #pragma unroll
            for (int p = 0; p < 4; p++) {
                LDSM_X4(bfr[2 * p][0], bfr[2 * p][1],
                        bfr[2 * p + 1][0], bfr[2 * p + 1][1],
                        stBase + bOff + p * MT_STRIDE + kOfs);
            }
            #pragma unroll
            for (int mt = 0; mt < 2; mt++)
                #pragma unroll
                for (int nt = 0; nt < 8; nt++)
                    MMA_TF32(acc[mt][nt], afr[mt], bfr[nt]);
        }

        __syncthreads();
        if (kt + 2 < NT) issue_tile(kt + 2, (kt + 2) % STAGES);
        CP_COMMIT();
    }

    // epilogue
    #pragma unroll
    for (int mt = 0; mt < 2; mt++) {
        const int row0 = bm + warp_m + mt * 16 + lq;
        #pragma unroll
        for (int nt = 0; nt < 8; nt++) {
            const int col = bn + warp_n + nt * 8 + 2 * lr;
            float b0 = 0.f, b1 = 0.f;
            if (bias) { b0 = bias[col]; b1 = bias[col + 1]; }
            float2 v01 = make_float2(acc[mt][nt][0] + b0, acc[mt][nt][1] + b1);
            float2 v23 = make_float2(acc[mt][nt][2] + b0, acc[mt][nt][3] + b1);
            *reinterpret_cast<float2*>(C + (size_t)row0 * N + col) = v01;
            *reinterpret_cast<float2*>(C + (size_t)(row0 + 8) * N + col) = v23;
        }
    }
}

// ---------------------------------------------------------------------------
// Weight pre-conversion to tf32 bit pattern (RNA)
// ---------------------------------------------------------------------------
__global__ void cvt_w_kernel(const float* __restrict__ src,
                             float* __restrict__ dst, int n)
{
    const int i = blockIdx.x * 256 + threadIdx.x;
    if (i < n) dst[i] = __uint_as_float(f2tf32(src[i]));
}

// ---------------------------------------------------------------------------
// Fused attention: one CTA per (b,n).
// ---------------------------------------------------------------------------
__global__ __launch_bounds__(256)
void attn_kernel(const float* __restrict__ q,
                 const float* __restrict__ kvr,
                 float* __restrict__ out)
{
    const int bn = blockIdx.x;
    const int t  = threadIdx.x;

    __shared__ float sq[Cc];
    __shared__ float skv[Vv][KVW];
    __shared__ float slog[Hh * Vv];
    __shared__ float sp[Hh][Vv];

    {
        const float4* src = reinterpret_cast<const float4*>(q + (size_t)bn * Cc);
        float4* dst = reinterpret_cast<float4*>(sq);
        for (int i = t; i < Cc / 4; i += 256) dst[i] = src[i];
    }
    {
        for (int i = t; i < Vv * KVW / 4; i += 256) {
            int v = i / (KVW / 4);
            int d4 = i % (KVW / 4);
            const float4* src = reinterpret_cast<const float4*>(
                kvr + ((size_t)v * (Bb * Nn) + bn) * KVW);
            reinterpret_cast<float4*>(skv[v])[d4] = src[d4];
        }
    }
    __syncthreads();

    #pragma unroll
    for (int rep = 0; rep < 3; rep++) {
        const int task = t + rep * 256;
        const int pair = task >> 3;
        const int sub  = task & 7;
        const int h = pair / Vv;
        const int v = pair % Vv;
        float a = 0.f;
        #pragma unroll
        for (int j = 0; j < 8; j++)
            a = fmaf(sq[h * HDd + sub * 8 + j], skv[v][sub * 8 + j], a);
        a += __shfl_down_sync(0xffffffffu, a, 4);
        a += __shfl_down_sync(0xffffffffu, a, 2);
        a += __shfl_down_sync(0xffffffffu, a, 1);
        if (sub == 0) slog[pair] = a * 0.125f;
    }
    __syncthreads();

    if (t < Hh) {
        float mx = -1e30f;
        #pragma unroll
        for (int v = 0; v < Vv; v++) mx = fmaxf(mx, slog[t * Vv + v]);
        float e[Vv];
        float s = 0.f;
        #pragma unroll
        for (int v = 0; v < Vv; v++) {
            e[v] = __expf(slog[t * Vv + v] - mx);
            s += e[v];
        }
        const float inv = 1.0f / s;
        #pragma unroll
        for (int v = 0; v < Vv; v++) sp[t][v] = e[v] * inv;
    }
    __syncthreads();

    #pragma unroll
    for (int rep = 0; rep < 3; rep++) {
        const int i = t + rep * 256;
        const int h = i / HDd;
        const int d = i % HDd;
        float a = 0.f;
        #pragma unroll
        for (int v = 0; v < Vv; v++)
            a = fmaf(sp[h][v], skv[v][HDd + d], a);
        out[(size_t)bn * Cc + i] = a;
    }
}

// ---------------------------------------------------------------------------
// Launch
// ---------------------------------------------------------------------------
extern "C" void kernel_launch(void* const* d_in, const int* in_sizes, int n_in,
                              void* d_out, int out_size)
{
    const float* x   = (const float*)d_in[0];
    const float* vp  = (const float*)d_in[1];
    const float* Wq  = (const float*)d_in[2];
    const float* Wkv = (const float*)d_in[3];
    const float* Wp  = (const float*)d_in[4];
    const float* bp  = (const float*)d_in[5];
    float* out = (float*)d_out;

    float *q, *kv, *ao, *wq, *wkv, *wp;
    cudaGetSymbolAddress((void**)&q,   g_q);
    cudaGetSymbolAddress((void**)&kv,  g_kv);
    cudaGetSymbolAddress((void**)&ao,  g_ao);
    cudaGetSymbolAddress((void**)&wq,  g_wq);
    cudaGetSymbolAddress((void**)&wkv, g_wkv);
    cudaGetSymbolAddress((void**)&wp,  g_wp);

    cudaFuncSetAttribute(tgemm_nt,
                         cudaFuncAttributeMaxDynamicSharedMemorySize,
                         GEMM_SMEM);

    // 0) pre-round weights to tf32 (removes all B-side cvts in the GEMMs)
    cvt_w_kernel<<<(Cc * Cc + 255) / 256, 256>>>(Wq, wq, Cc * Cc);
    cvt_w_kernel<<<(KVW * Cc + 255) / 256, 256>>>(Wkv, wkv, KVW * Cc);
    cvt_w_kernel<<<(Cc * Cc + 255) / 256, 256>>>(Wp, wp, Cc * Cc);

    // 1) q = x @ Wq^T
    tgemm_nt<<<dim3(Cc / 128, M1 / 128), 256, GEMM_SMEM>>>(
        x, wq, nullptr, q, M1, Cc, Cc);

    // 2) kv = vp_flat @ Wkv^T
    tgemm_nt<<<dim3(KVW / 128, MKV / 128), 256, GEMM_SMEM>>>(
        vp, wkv, nullptr, kv, MKV, KVW, Cc);

    // 3) fused attention per (b,n)
    attn_kernel<<<M1, 256>>>(q, kv, ao);

    // 4) out = ao @ Wproj^T + bproj
    tgemm_nt<<<dim3(Cc / 128, M1 / 128), 256, GEMM_SMEM>>>(
        ao, wp, bp, out, M1, Cc, Cc);
}

// round 6
// speedup vs baseline: 3.8037x; 1.0281x over previous
#include <cuda_runtime.h>
#include <cstdint>

// Problem constants
constexpr int Bb = 8;
constexpr int Nn = 1024;
constexpr int Cc = 768;
constexpr int Hh = 12;
constexpr int HDd = 64;
constexpr int Vv = 8;

constexpr int M1  = Bb * Nn;       // 8192
constexpr int MKV = Vv * Bb * Nn;  // 65536
constexpr int KVW = 2 * HDd;       // 128

// ---------------------------------------------------------------------------
// Scratch
// ---------------------------------------------------------------------------
__device__ float g_q[M1 * Cc];
__device__ float g_kv[MKV * KVW];
__device__ float g_ao[M1 * Cc];
__device__ float g_wq[Cc * Cc];     // tf32-rounded weights
__device__ float g_wkv[KVW * Cc];
__device__ float g_wp[Cc * Cc];

__device__ __forceinline__ uint32_t smem_u32(const void* p) {
    uint32_t a;
    asm("{ .reg .u64 t; cvta.to.shared.u64 t, %1; cvt.u32.u64 %0, t; }"
        : "=r"(a) : "l"(p));
    return a;
}

__device__ __forceinline__ unsigned f2tf32(float f) {
    unsigned r;
    asm volatile("cvt.rna.tf32.f32 %0, %1;" : "=r"(r) : "f"(f));
    return r;
}

#define CP_ASYNC16(dst, src)                                                  \
    asm volatile("cp.async.ca.shared.global [%0], [%1], 16;\n"                \
                 :: "r"(dst), "l"(src))
#define CP_COMMIT() asm volatile("cp.async.commit_group;\n" ::: "memory")
#define CP_WAIT2()  asm volatile("cp.async.wait_group 2;\n" ::: "memory")

#define MMA_TF32(c, a, b)                                                   \
    asm volatile(                                                           \
        "mma.sync.aligned.m16n8k8.row.col.f32.tf32.tf32.f32 "               \
        "{%0,%1,%2,%3}, {%4,%5,%6,%7}, {%8,%9}, {%0,%1,%2,%3};\n"           \
        : "+f"((c)[0]), "+f"((c)[1]), "+f"((c)[2]), "+f"((c)[3])            \
        : "r"((a)[0]), "r"((a)[1]), "r"((a)[2]), "r"((a)[3]),               \
          "r"((b)[0]), "r"((b)[1]))

#define LDSM_X4(r0, r1, r2, r3, addr)                                       \
    asm volatile(                                                           \
        "ldmatrix.sync.aligned.m8n8.x4.shared.b16 {%0,%1,%2,%3}, [%4];"     \
        : "=r"(r0), "=r"(r1), "=r"(r2), "=r"(r3) : "r"(addr))

// ---------------------------------------------------------------------------
// TF32 warp-MMA GEMM-NT, cp.async 4-stage pipeline, ONE sync per k-tile,
// ldmatrix fragments with intra-tile double buffering.
// CTA tile 128x128, BK=16, 8 warps (4M x 2N), warp tile 32x64.
// ---------------------------------------------------------------------------
constexpr int STAGES = 4;
constexpr int ROWPAD = 20;
constexpr int TILE_FLOATS = 128 * ROWPAD;
constexpr int GEMM_SMEM = STAGES * 2 * TILE_FLOATS * 4;  // 81920 bytes
constexpr int MT_STRIDE = 16 * ROWPAD * 4;

struct GemmPart {
    const float* A;
    const float* W;
    float* C;
    int M, N;
    int gx;       // grid cols for this part (N/128)
};

__device__ __forceinline__
void gemm_body(const float* __restrict__ A,
               const float* __restrict__ W,
               const float* __restrict__ bias,
               float* __restrict__ C,
               int N, int K, int bm, int bn,
               float* sm, uint32_t sb)
{
    const int t    = threadIdx.x;
    const int wid  = t >> 5;
    const int lane = t & 31;
    const int lq   = lane >> 2;
    const int lr   = lane & 3;

    const int warp_m = (wid & 3) * 32;
    const int warp_n = (wid >> 2) * 64;

    const int f0 = t, f1 = t + 256;
    const int r0 = f0 >> 2, c0 = f0 & 3;
    const int r1 = f1 >> 2, c1 = f1 & 3;

    const float* A0 = A + (size_t)(bm + r0) * K + c0 * 4;
    const float* A1 = A + (size_t)(bm + r1) * K + c1 * 4;
    const float* W0 = W + (size_t)(bn + r0) * K + c0 * 4;
    const float* W1 = W + (size_t)(bn + r1) * K + c1 * 4;

    const uint32_t dA0 = (uint32_t)(r0 * ROWPAD + c0 * 4) * 4;
    const uint32_t dA1 = (uint32_t)(r1 * ROWPAD + c1 * 4) * 4;
    const uint32_t dW0 = dA0 + TILE_FLOATS * 4;
    const uint32_t dW1 = dA1 + TILE_FLOATS * 4;

    auto issue_tile = [&](int kt) {
        const uint32_t base =
            sb + (uint32_t)(kt % STAGES) * 2 * TILE_FLOATS * 4;
        const size_t ko = (size_t)kt * 16;
        CP_ASYNC16(base + dA0, A0 + ko);
        CP_ASYNC16(base + dA1, A1 + ko);
        CP_ASYNC16(base + dW0, W0 + ko);
        CP_ASYNC16(base + dW1, W1 + ko);
    };

    const uint32_t aOff =
        (uint32_t)((warp_m + ((lane >> 3) & 1) * 8 + (lane & 7)) * ROWPAD
                   + (lane >> 4) * 4) * 4;
    const uint32_t bOff =
        (uint32_t)((warp_n + (lane >> 4) * 8 + (lane & 7)) * ROWPAD
                   + ((lane >> 3) & 1) * 4) * 4
        + TILE_FLOATS * 4;

    float acc[2][8][4];
    #pragma unroll
    for (int mt = 0; mt < 2; mt++)
        #pragma unroll
        for (int nt = 0; nt < 8; nt++)
            #pragma unroll
            for (int i = 0; i < 4; i++)
                acc[mt][nt][i] = 0.0f;

    const int NT = K / 16;

    issue_tile(0); CP_COMMIT();
    issue_tile(1); CP_COMMIT();
    issue_tile(2); CP_COMMIT();

    for (int kt = 0; kt < NT; kt++) {
        CP_WAIT2();
        __syncthreads();           // single barrier per k-tile

        // issue replacement tile into stage (kt-1)%STAGES — safe: last read
        // of that stage finished before the barrier above.
        if (kt + 3 < NT) issue_tile(kt + 3);
        CP_COMMIT();

        const uint32_t stBase =
            sb + (uint32_t)(kt % STAGES) * 2 * TILE_FLOATS * 4;

        // load kk=0 fragments
        unsigned afr[2][2][4];
        unsigned bfr[2][8][2];
        #pragma unroll
        for (int mt = 0; mt < 2; mt++)
            LDSM_X4(afr[0][mt][0], afr[0][mt][1], afr[0][mt][2], afr[0][mt][3],
                    stBase + aOff + mt * MT_STRIDE);
        #pragma unroll
        for (int p = 0; p < 4; p++)
            LDSM_X4(bfr[0][2 * p][0], bfr[0][2 * p][1],
                    bfr[0][2 * p + 1][0], bfr[0][2 * p + 1][1],
                    stBase + bOff + p * MT_STRIDE);

        // prefetch kk=8 fragments
        #pragma unroll
        for (int mt = 0; mt < 2; mt++)
            LDSM_X4(afr[1][mt][0], afr[1][mt][1], afr[1][mt][2], afr[1][mt][3],
                    stBase + aOff + mt * MT_STRIDE + 32);
        #pragma unroll
        for (int p = 0; p < 4; p++)
            LDSM_X4(bfr[1][2 * p][0], bfr[1][2 * p][1],
                    bfr[1][2 * p + 1][0], bfr[1][2 * p + 1][1],
                    stBase + bOff + p * MT_STRIDE + 32);

        #pragma unroll
        for (int half = 0; half < 2; half++) {
            #pragma unroll
            for (int mt = 0; mt < 2; mt++) {
                afr[half][mt][0] = f2tf32(__uint_as_float(afr[half][mt][0]));
                afr[half][mt][1] = f2tf32(__uint_as_float(afr[half][mt][1]));
                afr[half][mt][2] = f2tf32(__uint_as_float(afr[half][mt][2]));
                afr[half][mt][3] = f2tf32(__uint_as_float(afr[half][mt][3]));
            }
            #pragma unroll
            for (int mt = 0; mt < 2; mt++)
                #pragma unroll
                for (int nt = 0; nt < 8; nt++)
                    MMA_TF32(acc[mt][nt], afr[half][mt], bfr[half][nt]);
        }
    }

    // epilogue
    #pragma unroll
    for (int mt = 0; mt < 2; mt++) {
        const int row0 = bm + warp_m + mt * 16 + lq;
        #pragma unroll
        for (int nt = 0; nt < 8; nt++) {
            const int col = bn + warp_n + nt * 8 + 2 * lr;
            float b0 = 0.f, b1 = 0.f;
            if (bias) { b0 = bias[col]; b1 = bias[col + 1]; }
            float2 v01 = make_float2(acc[mt][nt][0] + b0, acc[mt][nt][1] + b1);
            float2 v23 = make_float2(acc[mt][nt][2] + b0, acc[mt][nt][3] + b1);
            *reinterpret_cast<float2*>(C + (size_t)row0 * N + col) = v01;
            *reinterpret_cast<float2*>(C + (size_t)(row0 + 8) * N + col) = v23;
        }
    }
}

// Merged q-GEMM + kv-GEMM (independent; joint grid for wave balance).
// blocks [0, 384): q = x @ wq^T   (M=8192, N=768)
// blocks [384, 896): kv = vp @ wkv^T (M=65536, N=128)
constexpr int QK_GRID_Q = (Cc / 128) * (M1 / 128);    // 384
constexpr int QK_GRID   = QK_GRID_Q + (MKV / 128);    // 896

__global__ __launch_bounds__(256, 2)
void qkv_gemm(const float* __restrict__ x,  const float* __restrict__ wq,
              const float* __restrict__ vp, const float* __restrict__ wkv,
              float* __restrict__ q, float* __restrict__ kv)
{
    extern __shared__ float sm[];
    const uint32_t sb = smem_u32(sm);
    const int bid = blockIdx.x;
    if (bid < QK_GRID_Q) {
        const int bx = bid % (Cc / 128);
        const int by = bid / (Cc / 128);
        gemm_body(x, wq, nullptr, q, Cc, Cc, by * 128, bx * 128, sm, sb);
    } else {
        const int by = bid - QK_GRID_Q;
        gemm_body(vp, wkv, nullptr, kv, KVW, Cc, by * 128, 0, sm, sb);
    }
}

__global__ __launch_bounds__(256, 2)
void proj_gemm(const float* __restrict__ ao, const float* __restrict__ wp,
               const float* __restrict__ bias, float* __restrict__ out)
{
    extern __shared__ float sm[];
    const uint32_t sb = smem_u32(sm);
    const int bx = blockIdx.x % (Cc / 128);
    const int by = blockIdx.x / (Cc / 128);
    gemm_body(ao, wp, bias, out, Cc, Cc, by * 128, bx * 128, sm, sb);
}

// ---------------------------------------------------------------------------
// Weight pre-conversion (all three weights in one launch)
// ---------------------------------------------------------------------------
constexpr int NW1 = Cc * Cc;
constexpr int NW2 = KVW * Cc;
constexpr int NW_TOT = NW1 + NW2 + NW1;

__global__ void cvt_w_kernel(const float* __restrict__ wq_in,
                             const float* __restrict__ wkv_in,
                             const float* __restrict__ wp_in,
                             float* __restrict__ wq_o,
                             float* __restrict__ wkv_o,
                             float* __restrict__ wp_o)
{
    const int i = blockIdx.x * 256 + threadIdx.x;
    if (i < NW1) {
        wq_o[i] = __uint_as_float(f2tf32(wq_in[i]));
    } else if (i < NW1 + NW2) {
        const int j = i - NW1;
        wkv_o[j] = __uint_as_float(f2tf32(wkv_in[j]));
    } else if (i < NW_TOT) {
        const int j = i - NW1 - NW2;
        wp_o[j] = __uint_as_float(f2tf32(wp_in[j]));
    }
}

// ---------------------------------------------------------------------------
// Fused attention: one CTA per (b,n).
// ---------------------------------------------------------------------------
__global__ __launch_bounds__(256)
void attn_kernel(const float* __restrict__ q,
                 const float* __restrict__ kvr,
                 float* __restrict__ out)
{
    const int bn = blockIdx.x;
    const int t  = threadIdx.x;

    __shared__ float sq[Cc];
    __shared__ float skv[Vv][KVW];
    __shared__ float slog[Hh * Vv];
    __shared__ float sp[Hh][Vv];

    {
        const float4* src = reinterpret_cast<const float4*>(q + (size_t)bn * Cc);
        float4* dst = reinterpret_cast<float4*>(sq);
        for (int i = t; i < Cc / 4; i += 256) dst[i] = src[i];
    }
    {
        for (int i = t; i < Vv * KVW / 4; i += 256) {
            int v = i / (KVW / 4);
            int d4 = i % (KVW / 4);
            const float4* src = reinterpret_cast<const float4*>(
                kvr + ((size_t)v * (Bb * Nn) + bn) * KVW);
            reinterpret_cast<float4*>(skv[v])[d4] = src[d4];
        }
    }
    __syncthreads();

    #pragma unroll
    for (int rep = 0; rep < 3; rep++) {
        const int task = t + rep * 256;
        const int pair = task >> 3;
        const int sub  = task & 7;
        const int h = pair / Vv;
        const int v = pair % Vv;
        float a = 0.f;
        #pragma unroll
        for (int j = 0; j < 8; j++)
            a = fmaf(sq[h * HDd + sub * 8 + j], skv[v][sub * 8 + j], a);
        a += __shfl_down_sync(0xffffffffu, a, 4);
        a += __shfl_down_sync(0xffffffffu, a, 2);
        a += __shfl_down_sync(0xffffffffu, a, 1);
        if (sub == 0) slog[pair] = a * 0.125f;
    }
    __syncthreads();

    if (t < Hh) {
        float mx = -1e30f;
        #pragma unroll
        for (int v = 0; v < Vv; v++) mx = fmaxf(mx, slog[t * Vv + v]);
        float e[Vv];
        float s = 0.f;
        #pragma unroll
        for (int v = 0; v < Vv; v++) {
            e[v] = __expf(slog[t * Vv + v] - mx);
            s += e[v];
        }
        const float inv = 1.0f / s;
        #pragma unroll
        for (int v = 0; v < Vv; v++) sp[t][v] = e[v] * inv;
    }
    __syncthreads();

    #pragma unroll
    for (int rep = 0; rep < 3; rep++) {
        const int i = t + rep * 256;
        const int h = i / HDd;
        const int d = i % HDd;
        float a = 0.f;
        #pragma unroll
        for (int v = 0; v < Vv; v++)
            a = fmaf(sp[h][v], skv[v][HDd + d], a);
        out[(size_t)bn * Cc + i] = a;
    }
}

// ---------------------------------------------------------------------------
// Launch
// ---------------------------------------------------------------------------
extern "C" void kernel_launch(void* const* d_in, const int* in_sizes, int n_in,
                              void* d_out, int out_size)
{
    const float* x   = (const float*)d_in[0];
    const float* vp  = (const float*)d_in[1];
    const float* Wq  = (const float*)d_in[2];
    const float* Wkv = (const float*)d_in[3];
    const float* Wp  = (const float*)d_in[4];
    const float* bp  = (const float*)d_in[5];
    float* out = (float*)d_out;

    float *q, *kv, *ao, *wq, *wkv, *wp;
    cudaGetSymbolAddress((void**)&q,   g_q);
    cudaGetSymbolAddress((void**)&kv,  g_kv);
    cudaGetSymbolAddress((void**)&ao,  g_ao);
    cudaGetSymbolAddress((void**)&wq,  g_wq);
    cudaGetSymbolAddress((void**)&wkv, g_wkv);
    cudaGetSymbolAddress((void**)&wp,  g_wp);

    cudaFuncSetAttribute(qkv_gemm,
                         cudaFuncAttributeMaxDynamicSharedMemorySize,
                         GEMM_SMEM);
    cudaFuncSetAttribute(proj_gemm,
                         cudaFuncAttributeMaxDynamicSharedMemorySize,
                         GEMM_SMEM);

    // 0) pre-round all weights to tf32
    cvt_w_kernel<<<(NW_TOT + 255) / 256, 256>>>(Wq, Wkv, Wp, wq, wkv, wp);

    // 1+2) q = x @ wq^T  and  kv = vp @ wkv^T  (merged grid)
    qkv_gemm<<<QK_GRID, 256, GEMM_SMEM>>>(x, wq, vp, wkv, q, kv);

    // 3) fused attention per (b,n)
    attn_kernel<<<M1, 256>>>(q, kv, ao);

    // 4) out = ao @ wp^T + bproj
    proj_gemm<<<(Cc / 128) * (M1 / 128), 256, GEMM_SMEM>>>(ao, wp, bp, out);
}